// round 1
// baseline (speedup 1.0000x reference)
#include <cuda_runtime.h>
#include <cuda_bf16.h>

// Conv2d VALID, stride 1:
//   x: [32, 64, 112, 112] f32, w: [128, 64, 3, 3] f32 -> out: [32, 128, 110, 110] f32
//
// Strategy (round 0): shared-memory tiled direct conv.
//   Block = 128 Cout x (16 wide x 8 tall) output pixels, 256 threads.
//   Each thread: 8 Cout x 8 consecutive-width pixels (64 fp32 accumulators).
//   K-loop over cin in chunks of 8; weights chunk transposed into smem as
//   [cin*9][cout] for conflict-free vectorized reads; input chunk in smem
//   as [cin][10 rows][20 cols(padded)].

namespace {

constexpr int CIN  = 64;
constexpr int COUT = 128;
constexpr int H    = 112;
constexpr int W    = 112;
constexpr int OH   = 110;
constexpr int OW   = 110;

constexpr int TW   = 16;   // output tile width
constexpr int TH   = 8;    // output tile height
constexpr int CCH  = 8;    // cin chunk

constexpr int IN_W  = TW + 2;        // 18 valid input cols per tile
constexpr int IN_WP = 20;            // padded row stride (16B aligned)
constexpr int IN_H  = TH + 2;        // 10 input rows per tile

__global__ __launch_bounds__(256, 2)
void conv3x3_kernel(const float* __restrict__ x,
                    const float* __restrict__ w,
                    float* __restrict__ out)
{
    __shared__ float w_s[CCH * 9 * COUT];          // [(c*9 + r*3 + s)][cout]  36864 B
    __shared__ float in_s[CCH][IN_H][IN_WP];       // 6400 B

    const int tid = threadIdx.x;
    const int ow0 = blockIdx.x * TW;
    const int oh0 = blockIdx.y * TH;
    const int b   = blockIdx.z;

    // thread -> (cout group, pixel group)
    const int g    = tid & 15;        // 16 pixel groups
    const int cg   = tid >> 4;        // 16 cout groups
    const int prow = g >> 1;          // 0..7 tile row
    const int pcol = (g & 1) * 8;     // 0 or 8: 8 consecutive cols
    const int co0  = cg * 8;

    float acc[8][8];
#pragma unroll
    for (int i = 0; i < 8; i++)
#pragma unroll
        for (int j = 0; j < 8; j++) acc[i][j] = 0.0f;

    const float* xb = x + (size_t)b * CIN * H * W;

    for (int c0 = 0; c0 < CIN; c0 += CCH) {
        __syncthreads();

        // ---- load weight chunk: CCH*9*COUT = 9216 elems, 36 per thread ----
        // smem index = t*128 + co  where t = c*9 + (r*3+s)
#pragma unroll
        for (int i = 0; i < 36; i++) {
            int idx = tid + i * 256;          // 0..9215
            int co  = idx & 127;
            int t   = idx >> 7;               // 0..71
            int c   = t / 9;
            int rs  = t - c * 9;
            w_s[idx] = w[((size_t)co * CIN + (c0 + c)) * 9 + rs];
        }

        // ---- load input chunk: CCH * IN_H * IN_W = 1440 elems ----
        for (int i = tid; i < CCH * IN_H * IN_W; i += 256) {
            int col = i % IN_W;
            int t   = i / IN_W;
            int row = t % IN_H;
            int c   = t / IN_H;
            int ih  = oh0 + row;
            int iw  = ow0 + col;
            float v = 0.0f;
            if (ih < H && iw < W)
                v = xb[((size_t)(c0 + c) * H + ih) * W + iw];
            in_s[c][row][col] = v;
        }

        __syncthreads();

        // ---- compute ----
#pragma unroll
        for (int c = 0; c < CCH; c++) {
#pragma unroll
            for (int r = 0; r < 3; r++) {
                float inr[10];
                const float* ip = &in_s[c][prow + r][pcol];
#pragma unroll
                for (int j = 0; j < 10; j++) inr[j] = ip[j];

#pragma unroll
                for (int s = 0; s < 3; s++) {
                    const float* wp = &w_s[(c * 9 + r * 3 + s) * COUT + co0];
                    float wr[8];
#pragma unroll
                    for (int i = 0; i < 8; i++) wr[i] = wp[i];
#pragma unroll
                    for (int i = 0; i < 8; i++)
#pragma unroll
                        for (int j = 0; j < 8; j++)
                            acc[i][j] = fmaf(wr[i], inr[j + s], acc[i][j]);
                }
            }
        }
    }

    // ---- store ----
    const int oh = oh0 + prow;
    if (oh < OH) {
#pragma unroll
        for (int i = 0; i < 8; i++) {
            float* op = out + (((size_t)b * COUT + co0 + i) * OH + oh) * OW + ow0 + pcol;
#pragma unroll
            for (int j = 0; j < 8; j++) {
                if (ow0 + pcol + j < OW) op[j] = acc[i][j];
            }
        }
    }
}

} // namespace

extern "C" void kernel_launch(void* const* d_in, const int* in_sizes, int n_in,
                              void* d_out, int out_size)
{
    const float* x   = (const float*)d_in[0];   // [32,64,112,112]
    const float* w   = (const float*)d_in[1];   // [128,64,3,3]
    float*       out = (float*)d_out;           // [32,128,110,110]

    dim3 grid((OW + TW - 1) / TW,   // 7
              (OH + TH - 1) / TH,   // 14
              32);                  // batch
    conv3x3_kernel<<<grid, 256>>>(x, w, out);
}

// round 5
// speedup vs baseline: 3.6035x; 3.6035x over previous
#include <cuda_runtime.h>
#include <cstdint>

// Conv2d VALID: x[32,64,112,112] f32, w[128,64,3,3] f32 -> out[32,128,110,110] f32
// Implicit GEMM via mma.sync.m16n8k8 tf32 (compute_103-safe; no 'a'-features).
//   Per CTA: M=128 (all couts), N=128 (2 oh rows x 64 ow), K=576 in 18 chunks of 32
//   (one 3x3 tap x 32 input channels per chunk). 256 threads = 8 warps (2m x 4n),
//   warp tile 64m x 32n, fragments loaded from smem with (k,k+4)-paired layout
//   so each operand fragment is a single LDS.64.

namespace {

constexpr int CIN = 64, COUT = 128, H = 112, W = 112, OH = 110, OW = 110;
constexpr int NCHUNK = 18;
constexpr int A_STRIDE = 36;          // 32 k floats + 4 pad
constexpr int B_STRIDE = 130;         // 128 n float2 + 2 pad

__device__ float g_A_pre[NCHUNK * 4096];   // [kc][co 128][perm-col 32] tf32

__device__ __forceinline__ float to_tf32(float v) {
    float o;
    asm("cvt.rna.tf32.f32 %0, %1;" : "=f"(o) : "f"(v));
    return o;
}

// ---------------- prep: weights -> tf32, (k,k+4)-paired col order ----------------
// col = g*8 + q*2 + e  represents k = g*8 + q + 4*e   (g:k8-group, q:0..3, e:0..1)
__global__ void prep_weights(const float* __restrict__ w) {
    int idx = blockIdx.x * 256 + threadIdx.x;   // 0 .. 18*4096-1
    int kc  = idx >> 12;
    int rem = idx & 4095;
    int co  = rem >> 5;
    int col = rem & 31;
    int g = col >> 3, t = col & 7, q = t >> 1, e = t & 1;
    int k = g * 8 + q + 4 * e;
    int ci = ((kc & 1) << 5) + k;
    int rs = kc >> 1;
    g_A_pre[idx] = to_tf32(w[((size_t)co * CIN + ci) * 9 + rs]);
}

// ---------------- main kernel ----------------
__global__ __launch_bounds__(256, 2)
void conv_mma(const float* __restrict__ x, float* __restrict__ out)
{
    __shared__ float As[128 * A_STRIDE];        // 18432 B
    __shared__ float2 Bs[16 * B_STRIDE];        // 16640 B  [g*4+q][n] = (k, k+4)

    const int tid  = threadIdx.x;
    const int wid  = tid >> 5;
    const int lane = tid & 31;
    const int wm   = wid >> 2;        // 0..1  (m half)
    const int wn   = wid & 3;         // 0..3  (n quarter)
    const int lr   = lane >> 2;       // 0..7
    const int lq   = lane & 3;        // 0..3

    const int ow0 = blockIdx.x * 64;
    const int oh0 = blockIdx.y * 2;
    const int bb  = blockIdx.z;

    float acc[4][4][4];
#pragma unroll
    for (int i = 0; i < 4; i++)
#pragma unroll
        for (int j = 0; j < 4; j++)
#pragma unroll
            for (int k = 0; k < 4; k++) acc[i][j][k] = 0.0f;

    const float* xb = x + (size_t)bb * CIN * H * W;

    for (int kc = 0; kc < NCHUNK; ++kc) {
        const int rs  = kc >> 1;
        const int r   = rs / 3;
        const int s   = rs - r * 3;
        const int ci0 = (kc & 1) << 5;

        __syncthreads();   // previous chunk's compute done before overwrite

        // ---- A: copy pre-permuted chunk (float4) ----
        {
            const float4* src = (const float4*)(g_A_pre + kc * 4096);
#pragma unroll
            for (int i = 0; i < 4; ++i) {
                int idx = tid + 256 * i;              // float4 index, 0..1023
                float4 v = src[idx];
                int row = idx >> 3;
                int col = (idx & 7) * 4;
                *(float4*)(As + row * A_STRIDE + col) = v;
            }
        }

        // ---- B: im2col gather, paired (k, k+4) per thread -> STS.64 ----
        {
#pragma unroll
            for (int i = 0; i < 8; ++i) {
                int flat = tid + 256 * i;             // 0..2047
                int n    = flat & 127;
                int pf   = flat >> 7;                 // 0..15 = g*4+q
                int g    = pf >> 2;
                int q    = pf & 3;
                int k0   = g * 8 + q;
                int c    = n & 63;
                int osub = n >> 6;
                int iw   = ow0 + c + s;
                int ih   = oh0 + osub + r;
                float v0 = 0.0f, v1 = 0.0f;
                if (iw < W) {
                    const float* p = xb + ((size_t)(ci0 + k0) * H + ih) * W + iw;
                    v0 = to_tf32(p[0]);
                    v1 = to_tf32(p[4 * H * W]);       // k0+4
                }
                Bs[pf * B_STRIDE + n] = make_float2(v0, v1);
            }
        }

        __syncthreads();

        // ---- compute: 4 k8-groups x (4 m-frags x 4 n-frags) mma ----
#pragma unroll
        for (int g = 0; g < 4; ++g) {
            uint32_t a[4][4];
#pragma unroll
            for (int mf = 0; mf < 4; ++mf) {
                int row = wm * 64 + mf * 16 + lr;
                const float2* p0 = (const float2*)(As + row * A_STRIDE + g * 8 + lq * 2);
                const float2* p1 = (const float2*)(As + (row + 8) * A_STRIDE + g * 8 + lq * 2);
                float2 v02 = *p0;   // (a0, a2)
                float2 v13 = *p1;   // (a1, a3)
                a[mf][0] = __float_as_uint(v02.x);
                a[mf][1] = __float_as_uint(v13.x);
                a[mf][2] = __float_as_uint(v02.y);
                a[mf][3] = __float_as_uint(v13.y);
            }
            uint32_t b[4][2];
#pragma unroll
            for (int nf = 0; nf < 4; ++nf) {
                float2 v = Bs[(g * 4 + lq) * B_STRIDE + wn * 32 + nf * 8 + lr];
                b[nf][0] = __float_as_uint(v.x);
                b[nf][1] = __float_as_uint(v.y);
            }
#pragma unroll
            for (int mf = 0; mf < 4; ++mf)
#pragma unroll
                for (int nf = 0; nf < 4; ++nf) {
                    asm volatile(
                        "mma.sync.aligned.m16n8k8.row.col.f32.tf32.tf32.f32 "
                        "{%0,%1,%2,%3}, {%4,%5,%6,%7}, {%8,%9}, {%0,%1,%2,%3};"
                        : "+f"(acc[mf][nf][0]), "+f"(acc[mf][nf][1]),
                          "+f"(acc[mf][nf][2]), "+f"(acc[mf][nf][3])
                        : "r"(a[mf][0]), "r"(a[mf][1]), "r"(a[mf][2]), "r"(a[mf][3]),
                          "r"(b[nf][0]), "r"(b[nf][1]));
                }
        }
    }

    // ---- epilogue: direct STG.64 (nglob even -> ow even -> pairs stay in-bounds) ----
#pragma unroll
    for (int mf = 0; mf < 4; ++mf) {
#pragma unroll
        for (int nf = 0; nf < 4; ++nf) {
            int nglob = wn * 32 + nf * 8 + lq * 2;    // 0..126 even
            int osub  = nglob >> 6;
            int ow    = ow0 + (nglob & 63);
            int oh    = oh0 + osub;
            if (ow < OW) {
                int co0 = wm * 64 + mf * 16 + lr;
                float* p0 = out + (((size_t)bb * COUT + co0) * OH + oh) * OW + ow;
                *(float2*)p0 = make_float2(acc[mf][nf][0], acc[mf][nf][1]);
                float* p1 = p0 + (size_t)8 * OH * OW;
                *(float2*)p1 = make_float2(acc[mf][nf][2], acc[mf][nf][3]);
            }
        }
    }
}

} // namespace

extern "C" void kernel_launch(void* const* d_in, const int* in_sizes, int n_in,
                              void* d_out, int out_size)
{
    const float* x = (const float*)d_in[0];
    const float* w = (const float*)d_in[1];
    float* out = (float*)d_out;

    prep_weights<<<NCHUNK * 4096 / 256, 256>>>(w);

    dim3 grid(2, 55, 32);   // ow tiles (2x64 covers 110), oh pairs, batch
    conv_mma<<<grid, 256>>>(x, out);
}